// round 6
// baseline (speedup 1.0000x reference)
#include <cuda_runtime.h>
#include <math.h>

#define Nn   6000
#define Ee   192000
#define CINc 32
#define CHID 64
#define Kk   125          // 5^3 kernel weights
// S = 8 corners per edge

// ---------------- device scratch (no allocation allowed) ----------------
__device__ float g_Tx[(size_t)Nn * Kk * CINc];   // 24M floats, pre-scaled by 1/deg
__device__ float g_Th[(size_t)Nn * Kk * CHID];   // 48M floats, pre-scaled by 1/deg
__device__ int   g_deg[Nn];
__device__ int   g_fill[Nn];
__device__ int   g_rowstart[Nn + 1];
__device__ int   g_csr[Ee];
__device__ int   g_bidx[Ee * 8];
__device__ float g_bval[Ee * 8];
__device__ float g_XR[Nn * CHID];
__device__ float g_XZ[Nn * CHID];
__device__ float g_XN[Nn * CHID];
__device__ float g_HR[Nn * CHID];
__device__ float g_HZ[Nn * CHID];

// ---------------- f32x2 packed math helpers ----------------
__device__ __forceinline__ unsigned long long ffma2(unsigned long long a,
                                                    unsigned long long b,
                                                    unsigned long long c) {
    unsigned long long d;
    asm("fma.rn.f32x2 %0, %1, %2, %3;" : "=l"(d) : "l"(a), "l"(b), "l"(c));
    return d;
}
__device__ __forceinline__ unsigned long long packdup(float f) {
    unsigned long long r;
    asm("mov.b64 %0, {%1, %1};" : "=l"(r) : "f"(f));
    return r;
}
__device__ __forceinline__ void unpack2(unsigned long long v, float& lo, float& hi) {
    asm("mov.b64 {%0, %1}, %2;" : "=f"(lo), "=f"(hi) : "l"(v));
}

// ---------------- kernel 0: zero per-call counters ----------------
__global__ void k_zero() {
    int i = blockIdx.x * blockDim.x + threadIdx.x;
    if (i < Nn) { g_deg[i] = 0; g_fill[i] = 0; }
}

// ---------------- kernel 1: per-edge basis/index + degree histogram ----------------
__global__ void k_edge(const float* __restrict__ attr, const int* __restrict__ ei) {
    int e = blockIdx.x * blockDim.x + threadIdx.x;
    if (e >= Ee) return;
    float fr[3]; int i0[3];
#pragma unroll
    for (int d = 0; d < 3; d++) {
        float u = attr[e * 3 + d] * 4.0f;          // (KS-1) intervals
        int i = (int)floorf(u);
        i = i < 0 ? 0 : (i > 3 ? 3 : i);           // clip to [0, KS-2]
        fr[d] = u - (float)i;
        i0[d] = i;
    }
#pragma unroll
    for (int s = 0; s < 8; s++) {
        int b0 = s & 1, b1 = (s >> 1) & 1, b2 = (s >> 2) & 1;
        // strides = KS**[2,1,0] applied to dims [0,1,2]
        int idx = (i0[0] + b0) * 25 + (i0[1] + b1) * 5 + (i0[2] + b2);
        float w = (b0 ? fr[0] : 1.0f - fr[0]) *
                  (b1 ? fr[1] : 1.0f - fr[1]) *
                  (b2 ? fr[2] : 1.0f - fr[2]);
        g_bidx[e * 8 + s] = idx;
        g_bval[e * 8 + s] = w;
    }
    atomicAdd(&g_deg[ei[Ee + e]], 1);              // dst = row 1
}

// ---------------- kernel 2: exclusive scan of degrees (single block) ----------------
__global__ void k_scan() {
    __shared__ int sh[1024];
    int tid = threadIdx.x;
    const int CH = 6;                               // 1024*6 >= 6000
    int base = tid * CH;
    int local[CH];
    int sum = 0;
#pragma unroll
    for (int q = 0; q < CH; q++) {
        int i = base + q;
        int v = (i < Nn) ? g_deg[i] : 0;
        local[q] = sum;
        sum += v;
    }
    sh[tid] = sum;
    __syncthreads();
    for (int off = 1; off < 1024; off <<= 1) {
        int v = 0;
        if (tid >= off) v = sh[tid - off];
        __syncthreads();
        sh[tid] += v;
        __syncthreads();
    }
    int excl = (tid > 0) ? sh[tid - 1] : 0;
#pragma unroll
    for (int q = 0; q < CH; q++) {
        int i = base + q;
        if (i < Nn) g_rowstart[i] = excl + local[q];
    }
    if (tid == 1023) g_rowstart[Nn] = sh[1023];
}

// ---------------- kernel 3: CSR fill ----------------
__global__ void k_fill(const int* __restrict__ ei) {
    int e = blockIdx.x * blockDim.x + threadIdx.x;
    if (e >= Ee) return;
    int dst = ei[Ee + e];
    int p = atomicAdd(&g_fill[dst], 1);
    g_csr[g_rowstart[dst] + p] = e;
}

// ---------------- kernel 4: per-node scatter into T (no atomics), pre-scaled by 1/deg ----------------
__global__ __launch_bounds__(96) void k_scatter(const float* __restrict__ x,
                                                const float* __restrict__ hidden,
                                                const int* __restrict__ ei) {
    __shared__ float Tsh[Kk * 96];                  // 48000 bytes
    int n = blockIdx.x;
    int c = threadIdx.x;                            // channel lane: 0..31 -> x, 32..95 -> hidden
#pragma unroll 5
    for (int k = 0; k < Kk; k++) Tsh[k * 96 + c] = 0.0f;
    int rs = g_rowstart[n], re = g_rowstart[n + 1];
    float inv = 1.0f / (float)max(re - rs, 1);
    __syncthreads();

    for (int j = rs; j < re; j++) {
        int e   = __ldg(&g_csr[j]);
        int src = __ldg(&ei[e]);                    // src = row 0
        float xv = (c < CINc) ? __ldg(&x[src * CINc + c])
                              : __ldg(&hidden[src * CHID + (c - CINc)]);
        const int4*   bip = (const int4*)(g_bidx + e * 8);
        const float4* bvp = (const float4*)(g_bval + e * 8);
        int4   ia = __ldg(bip),     ib = __ldg(bip + 1);
        float4 va = __ldg(bvp),     vb = __ldg(bvp + 1);
        // 8 corner indices within an edge are distinct; each thread owns column c
        Tsh[ia.x * 96 + c] += va.x * xv;
        Tsh[ia.y * 96 + c] += va.y * xv;
        Tsh[ia.z * 96 + c] += va.z * xv;
        Tsh[ia.w * 96 + c] += va.w * xv;
        Tsh[ib.x * 96 + c] += vb.x * xv;
        Tsh[ib.y * 96 + c] += vb.y * xv;
        Tsh[ib.z * 96 + c] += vb.z * xv;
        Tsh[ib.w * 96 + c] += vb.w * xv;
    }
    __syncthreads();

    if (c < CINc) {
        float* o = g_Tx + (size_t)n * (Kk * CINc) + c;
#pragma unroll 5
        for (int k = 0; k < Kk; k++) o[k * CINc] = Tsh[k * 96 + c] * inv;
    } else {
        float* o = g_Th + (size_t)n * (Kk * CHID) + (c - CINc);
#pragma unroll 5
        for (int k = 0; k < Kk; k++) o[k * CHID] = Tsh[k * 96 + c] * inv;
    }
}

// ---------------- kernel 5: GEMM  C[M,64] = [T/deg | X2] @ [W ; root] + bias ----------------
// BM=64, BN=64, BK=16, 64 threads, 8x8 thread tile, f32x2 row-pair accumulators.
// grid.y selects one of the 5 convs (hn-conv is dead in the reference).
__global__ __launch_bounds__(64) void k_gemm(
    const float* __restrict__ x, const float* __restrict__ hidden,
    const float* __restrict__ Wxr, const float* __restrict__ Rxr, const float* __restrict__ Bxr,
    const float* __restrict__ Wxz, const float* __restrict__ Rxz, const float* __restrict__ Bxz,
    const float* __restrict__ Wxn, const float* __restrict__ Rxn, const float* __restrict__ Bxn,
    const float* __restrict__ Whr, const float* __restrict__ Rhr, const float* __restrict__ Bhr,
    const float* __restrict__ Whz, const float* __restrict__ Rhz, const float* __restrict__ Bhz)
{
    const float *A, *X2, *W, *R, *B;
    float* O;
    int Kd, C2;
    switch (blockIdx.y) {
        case 0:  A = g_Tx; X2 = x;      W = Wxr; R = Rxr; B = Bxr; O = g_XR; Kd = Kk * CINc; C2 = CINc; break;
        case 1:  A = g_Tx; X2 = x;      W = Wxz; R = Rxz; B = Bxz; O = g_XZ; Kd = Kk * CINc; C2 = CINc; break;
        case 2:  A = g_Tx; X2 = x;      W = Wxn; R = Rxn; B = Bxn; O = g_XN; Kd = Kk * CINc; C2 = CINc; break;
        case 3:  A = g_Th; X2 = hidden; W = Whr; R = Rhr; B = Bhr; O = g_HR; Kd = Kk * CHID; C2 = CHID; break;
        default: A = g_Th; X2 = hidden; W = Whz; R = Rhz; B = Bhz; O = g_HZ; Kd = Kk * CHID; C2 = CHID; break;
    }
    __shared__ float As[16][64];
    __shared__ float Bs[16][64];
    int t = threadIdx.x, tx = t & 7, ty = t >> 3;
    int row0 = blockIdx.x * 64;
    int m = row0 + t;
    int kbrow = t >> 2, c0 = (t & 3) * 16;

    unsigned long long acc[4][8];
#pragma unroll
    for (int i = 0; i < 4; i++)
#pragma unroll
        for (int j = 0; j < 8; j++) acc[i][j] = 0ull;

    int ntile = (Kd + C2) >> 4;                     // 252 (x) or 504 (h), no tile straddles Kd
    float4 av[4], bv[4];

    auto loadT = [&](int kt) {
        int k0 = kt * 16;
        if (m < Nn) {
            const float* ap = (k0 < Kd) ? (A + (size_t)m * Kd + k0)
                                        : (X2 + (size_t)m * C2 + (k0 - Kd));
#pragma unroll
            for (int q = 0; q < 4; q++) av[q] = __ldg((const float4*)ap + q);
        } else {
            float4 z = make_float4(0.f, 0.f, 0.f, 0.f);
            av[0] = z; av[1] = z; av[2] = z; av[3] = z;
        }
        int kk = k0 + kbrow;
        const float* bp = (kk < Kd) ? (W + (size_t)kk * 64 + c0)
                                    : (R + (size_t)(kk - Kd) * 64 + c0);
#pragma unroll
        for (int q = 0; q < 4; q++) bv[q] = __ldg((const float4*)bp + q);
    };
    auto storeT = [&]() {
#pragma unroll
        for (int q = 0; q < 4; q++) {
            As[4 * q + 0][t] = av[q].x;
            As[4 * q + 1][t] = av[q].y;
            As[4 * q + 2][t] = av[q].z;
            As[4 * q + 3][t] = av[q].w;
        }
#pragma unroll
        for (int q = 0; q < 4; q++) *(float4*)&Bs[kbrow][c0 + 4 * q] = bv[q];
    };

    loadT(0);
    storeT();
    __syncthreads();
    for (int kt = 0; kt < ntile; kt++) {
        bool more = (kt + 1 < ntile);
        if (more) loadT(kt + 1);                    // LDG latency overlapped with compute
#pragma unroll
        for (int k = 0; k < 16; k++) {
            unsigned long long a2[4];
#pragma unroll
            for (int rp = 0; rp < 4; rp++)
                a2[rp] = *(const unsigned long long*)&As[k][ty * 8 + 2 * rp];
            float4 bA = *(const float4*)&Bs[k][tx * 8];
            float4 bB = *(const float4*)&Bs[k][tx * 8 + 4];
            unsigned long long bb[8];
            bb[0] = packdup(bA.x); bb[1] = packdup(bA.y);
            bb[2] = packdup(bA.z); bb[3] = packdup(bA.w);
            bb[4] = packdup(bB.x); bb[5] = packdup(bB.y);
            bb[6] = packdup(bB.z); bb[7] = packdup(bB.w);
#pragma unroll
            for (int rp = 0; rp < 4; rp++)
#pragma unroll
                for (int j = 0; j < 8; j++)
                    acc[rp][j] = ffma2(a2[rp], bb[j], acc[rp][j]);
        }
        __syncthreads();
        if (more) { storeT(); __syncthreads(); }
    }

    // epilogue: add bias, write two rows per row-pair
    float bias8[8];
#pragma unroll
    for (int j = 0; j < 8; j++) bias8[j] = __ldg(&B[tx * 8 + j]);
#pragma unroll
    for (int rp = 0; rp < 4; rp++) {
        float r0[8], r1[8];
#pragma unroll
        for (int j = 0; j < 8; j++) {
            float lo, hi;
            unpack2(acc[rp][j], lo, hi);
            r0[j] = lo + bias8[j];
            r1[j] = hi + bias8[j];
        }
        int m0 = row0 + ty * 8 + 2 * rp;
        if (m0 < Nn) {
            float4* op = (float4*)(O + (size_t)m0 * 64 + tx * 8);
            op[0] = make_float4(r0[0], r0[1], r0[2], r0[3]);
            op[1] = make_float4(r0[4], r0[5], r0[6], r0[7]);
        }
        if (m0 + 1 < Nn) {
            float4* op = (float4*)(O + (size_t)(m0 + 1) * 64 + tx * 8);
            op[0] = make_float4(r1[0], r1[1], r1[2], r1[3]);
            op[1] = make_float4(r1[4], r1[5], r1[6], r1[7]);
        }
    }
}

// ---------------- kernel 6: GRU gate fusion ----------------
__global__ void k_gates(const float* __restrict__ hidden, float* __restrict__ out) {
    int i = blockIdx.x * blockDim.x + threadIdx.x;
    if (i >= Nn * CHID) return;
    float xr = g_XR[i], hr = g_HR[i];
    float xz = g_XZ[i], hz = g_HZ[i];
    float xn = g_XN[i], h = hidden[i];
    float r = 1.0f / (1.0f + expf(-(xr + hr)));
    float z = 1.0f / (1.0f + expf(-(xz + hz)));
    float n = tanhf(xn + r * hr);                   // faithful to the reference's hr reuse
    out[i] = (1.0f - z) * n + z * h;
}

// ---------------- launch ----------------
extern "C" void kernel_launch(void* const* d_in, const int* in_sizes, int n_in,
                              void* d_out, int out_size) {
    const float* x      = (const float*)d_in[0];
    const float* hidden = (const float*)d_in[1];
    const int*   ei     = (const int*)d_in[2];
    const float* attr   = (const float*)d_in[3];
    const float* Wxr = (const float*)d_in[4];
    const float* Rxr = (const float*)d_in[5];
    const float* Bxr = (const float*)d_in[6];
    const float* Whr = (const float*)d_in[7];
    const float* Rhr = (const float*)d_in[8];
    const float* Bhr = (const float*)d_in[9];
    const float* Wxz = (const float*)d_in[10];
    const float* Rxz = (const float*)d_in[11];
    const float* Bxz = (const float*)d_in[12];
    const float* Whz = (const float*)d_in[13];
    const float* Rhz = (const float*)d_in[14];
    const float* Bhz = (const float*)d_in[15];
    const float* Wxn = (const float*)d_in[16];
    const float* Rxn = (const float*)d_in[17];
    const float* Bxn = (const float*)d_in[18];
    // d_in[19..21] = W_hn/root_hn/b_hn: dead in the reference (hr reuse bug), unused.
    float* out = (float*)d_out;
    (void)in_sizes; (void)n_in; (void)out_size;

    k_zero<<<(Nn + 255) / 256, 256>>>();
    k_edge<<<(Ee + 255) / 256, 256>>>(attr, ei);
    k_scan<<<1, 1024>>>();
    k_fill<<<(Ee + 255) / 256, 256>>>(ei);
    k_scatter<<<Nn, 96>>>(x, hidden, ei);
    dim3 gg((Nn + 63) / 64, 5);
    k_gemm<<<gg, 64>>>(x, hidden,
                       Wxr, Rxr, Bxr,
                       Wxz, Rxz, Bxz,
                       Wxn, Rxn, Bxn,
                       Whr, Rhr, Bhr,
                       Whz, Rhz, Bhz);
    k_gates<<<(Nn * CHID + 255) / 256, 256>>>(hidden, out);
}

// round 7
// speedup vs baseline: 1.0525x; 1.0525x over previous
#include <cuda_runtime.h>
#include <math.h>

#define Nn   6000
#define Ee   192000
#define CINc 32
#define CHID 64
#define Kk   125          // 5^3 kernel weights
// S = 8 corners per edge

// ---------------- device scratch (no allocation allowed) ----------------
__device__ float g_Tx[(size_t)Nn * Kk * CINc];   // 24M floats, pre-scaled by 1/deg
__device__ float g_Th[(size_t)Nn * Kk * CHID];   // 48M floats, pre-scaled by 1/deg
__device__ int   g_deg[Nn];
__device__ int   g_fill[Nn];
__device__ int   g_rowstart[Nn + 1];
__device__ int   g_csr[Ee];
__device__ int   g_bidx[Ee * 8];
__device__ float g_bval[Ee * 8];
__device__ float g_XR[Nn * CHID];
__device__ float g_XZ[Nn * CHID];
__device__ float g_XN[Nn * CHID];
__device__ float g_HR[Nn * CHID];
__device__ float g_HZ[Nn * CHID];

// ---------------- f32x2 packed math helpers ----------------
__device__ __forceinline__ unsigned long long ffma2(unsigned long long a,
                                                    unsigned long long b,
                                                    unsigned long long c) {
    unsigned long long d;
    asm("fma.rn.f32x2 %0, %1, %2, %3;" : "=l"(d) : "l"(a), "l"(b), "l"(c));
    return d;
}
__device__ __forceinline__ unsigned long long packdup(float f) {
    unsigned long long r;
    asm("mov.b64 %0, {%1, %1};" : "=l"(r) : "f"(f));
    return r;
}
__device__ __forceinline__ void unpack2(unsigned long long v, float& lo, float& hi) {
    asm("mov.b64 {%0, %1}, %2;" : "=f"(lo), "=f"(hi) : "l"(v));
}

// ---------------- kernel 0: zero per-call counters ----------------
__global__ void k_zero() {
    int i = blockIdx.x * blockDim.x + threadIdx.x;
    if (i < Nn) { g_deg[i] = 0; g_fill[i] = 0; }
}

// ---------------- kernel 1: per-edge basis/index + degree histogram ----------------
__global__ void k_edge(const float* __restrict__ attr, const int* __restrict__ ei) {
    int e = blockIdx.x * blockDim.x + threadIdx.x;
    if (e >= Ee) return;
    float fr[3]; int i0[3];
#pragma unroll
    for (int d = 0; d < 3; d++) {
        float u = attr[e * 3 + d] * 4.0f;          // (KS-1) intervals
        int i = (int)floorf(u);
        i = i < 0 ? 0 : (i > 3 ? 3 : i);           // clip to [0, KS-2]
        fr[d] = u - (float)i;
        i0[d] = i;
    }
#pragma unroll
    for (int s = 0; s < 8; s++) {
        int b0 = s & 1, b1 = (s >> 1) & 1, b2 = (s >> 2) & 1;
        // strides = KS**[2,1,0] applied to dims [0,1,2]
        int idx = (i0[0] + b0) * 25 + (i0[1] + b1) * 5 + (i0[2] + b2);
        float w = (b0 ? fr[0] : 1.0f - fr[0]) *
                  (b1 ? fr[1] : 1.0f - fr[1]) *
                  (b2 ? fr[2] : 1.0f - fr[2]);
        g_bidx[e * 8 + s] = idx;
        g_bval[e * 8 + s] = w;
    }
    atomicAdd(&g_deg[ei[Ee + e]], 1);              // dst = row 1
}

// ---------------- kernel 2: exclusive scan of degrees (single block) ----------------
__global__ void k_scan() {
    __shared__ int sh[1024];
    int tid = threadIdx.x;
    const int CH = 6;                               // 1024*6 >= 6000
    int base = tid * CH;
    int local[CH];
    int sum = 0;
#pragma unroll
    for (int q = 0; q < CH; q++) {
        int i = base + q;
        int v = (i < Nn) ? g_deg[i] : 0;
        local[q] = sum;
        sum += v;
    }
    sh[tid] = sum;
    __syncthreads();
    for (int off = 1; off < 1024; off <<= 1) {
        int v = 0;
        if (tid >= off) v = sh[tid - off];
        __syncthreads();
        sh[tid] += v;
        __syncthreads();
    }
    int excl = (tid > 0) ? sh[tid - 1] : 0;
#pragma unroll
    for (int q = 0; q < CH; q++) {
        int i = base + q;
        if (i < Nn) g_rowstart[i] = excl + local[q];
    }
    if (tid == 1023) g_rowstart[Nn] = sh[1023];
}

// ---------------- kernel 3: CSR fill ----------------
__global__ void k_fill(const int* __restrict__ ei) {
    int e = blockIdx.x * blockDim.x + threadIdx.x;
    if (e >= Ee) return;
    int dst = ei[Ee + e];
    int p = atomicAdd(&g_fill[dst], 1);
    g_csr[g_rowstart[dst] + p] = e;
}

// ---------------- kernel 4: per-node scatter into T (no atomics), pre-scaled by 1/deg ----------------
__global__ __launch_bounds__(96) void k_scatter(const float* __restrict__ x,
                                                const float* __restrict__ hidden,
                                                const int* __restrict__ ei) {
    __shared__ float Tsh[Kk * 96];                  // 48000 bytes
    int n = blockIdx.x;
    int c = threadIdx.x;                            // channel lane: 0..31 -> x, 32..95 -> hidden
#pragma unroll 5
    for (int k = 0; k < Kk; k++) Tsh[k * 96 + c] = 0.0f;
    int rs = g_rowstart[n], re = g_rowstart[n + 1];
    float inv = 1.0f / (float)max(re - rs, 1);
    __syncthreads();

    for (int j = rs; j < re; j++) {
        int e   = __ldg(&g_csr[j]);
        int src = __ldg(&ei[e]);                    // src = row 0
        float xv = (c < CINc) ? __ldg(&x[src * CINc + c])
                              : __ldg(&hidden[src * CHID + (c - CINc)]);
        const int4*   bip = (const int4*)(g_bidx + e * 8);
        const float4* bvp = (const float4*)(g_bval + e * 8);
        int4   ia = __ldg(bip),     ib = __ldg(bip + 1);
        float4 va = __ldg(bvp),     vb = __ldg(bvp + 1);
        // 8 corner indices within an edge are distinct; each thread owns column c
        Tsh[ia.x * 96 + c] += va.x * xv;
        Tsh[ia.y * 96 + c] += va.y * xv;
        Tsh[ia.z * 96 + c] += va.z * xv;
        Tsh[ia.w * 96 + c] += va.w * xv;
        Tsh[ib.x * 96 + c] += vb.x * xv;
        Tsh[ib.y * 96 + c] += vb.y * xv;
        Tsh[ib.z * 96 + c] += vb.z * xv;
        Tsh[ib.w * 96 + c] += vb.w * xv;
    }
    __syncthreads();

    if (c < CINc) {
        float* o = g_Tx + (size_t)n * (Kk * CINc) + c;
#pragma unroll 5
        for (int k = 0; k < Kk; k++) o[k * CINc] = Tsh[k * 96 + c] * inv;
    } else {
        float* o = g_Th + (size_t)n * (Kk * CHID) + (c - CINc);
#pragma unroll 5
        for (int k = 0; k < Kk; k++) o[k * CHID] = Tsh[k * 96 + c] * inv;
    }
}

// ---------------- kernel 5: GEMM  C[M,64] = [T/deg | X2] @ [W ; root] + bias ----------------
// BM=64, BN=64, BK=16, 64 threads, 8x8 thread tile, f32x2 row-pair accumulators.
// grid.y selects one of the 5 convs (hn-conv is dead in the reference).
__global__ __launch_bounds__(64) void k_gemm(
    const float* __restrict__ x, const float* __restrict__ hidden,
    const float* __restrict__ Wxr, const float* __restrict__ Rxr, const float* __restrict__ Bxr,
    const float* __restrict__ Wxz, const float* __restrict__ Rxz, const float* __restrict__ Bxz,
    const float* __restrict__ Wxn, const float* __restrict__ Rxn, const float* __restrict__ Bxn,
    const float* __restrict__ Whr, const float* __restrict__ Rhr, const float* __restrict__ Bhr,
    const float* __restrict__ Whz, const float* __restrict__ Rhz, const float* __restrict__ Bhz)
{
    const float *A, *X2, *W, *R, *B;
    float* O;
    int Kd, C2;
    switch (blockIdx.y) {
        case 0:  A = g_Tx; X2 = x;      W = Wxr; R = Rxr; B = Bxr; O = g_XR; Kd = Kk * CINc; C2 = CINc; break;
        case 1:  A = g_Tx; X2 = x;      W = Wxz; R = Rxz; B = Bxz; O = g_XZ; Kd = Kk * CINc; C2 = CINc; break;
        case 2:  A = g_Tx; X2 = x;      W = Wxn; R = Rxn; B = Bxn; O = g_XN; Kd = Kk * CINc; C2 = CINc; break;
        case 3:  A = g_Th; X2 = hidden; W = Whr; R = Rhr; B = Bhr; O = g_HR; Kd = Kk * CHID; C2 = CHID; break;
        default: A = g_Th; X2 = hidden; W = Whz; R = Rhz; B = Bhz; O = g_HZ; Kd = Kk * CHID; C2 = CHID; break;
    }
    __shared__ float As[16][64];
    __shared__ float Bs[16][64];
    int t = threadIdx.x, tx = t & 7, ty = t >> 3;
    int row0 = blockIdx.x * 64;
    int m = row0 + t;
    int kbrow = t >> 2, c0 = (t & 3) * 16;

    unsigned long long acc[4][8];
#pragma unroll
    for (int i = 0; i < 4; i++)
#pragma unroll
        for (int j = 0; j < 8; j++) acc[i][j] = 0ull;

    int ntile = (Kd + C2) >> 4;                     // 252 (x) or 504 (h), no tile straddles Kd
    float4 av[4], bv[4];

    auto loadT = [&](int kt) {
        int k0 = kt * 16;
        if (m < Nn) {
            const float* ap = (k0 < Kd) ? (A + (size_t)m * Kd + k0)
                                        : (X2 + (size_t)m * C2 + (k0 - Kd));
#pragma unroll
            for (int q = 0; q < 4; q++) av[q] = __ldg((const float4*)ap + q);
        } else {
            float4 z = make_float4(0.f, 0.f, 0.f, 0.f);
            av[0] = z; av[1] = z; av[2] = z; av[3] = z;
        }
        int kk = k0 + kbrow;
        const float* bp = (kk < Kd) ? (W + (size_t)kk * 64 + c0)
                                    : (R + (size_t)(kk - Kd) * 64 + c0);
#pragma unroll
        for (int q = 0; q < 4; q++) bv[q] = __ldg((const float4*)bp + q);
    };
    auto storeT = [&]() {
#pragma unroll
        for (int q = 0; q < 4; q++) {
            As[4 * q + 0][t] = av[q].x;
            As[4 * q + 1][t] = av[q].y;
            As[4 * q + 2][t] = av[q].z;
            As[4 * q + 3][t] = av[q].w;
        }
#pragma unroll
        for (int q = 0; q < 4; q++) *(float4*)&Bs[kbrow][c0 + 4 * q] = bv[q];
    };

    loadT(0);
    storeT();
    __syncthreads();
    for (int kt = 0; kt < ntile; kt++) {
        bool more = (kt + 1 < ntile);
        if (more) loadT(kt + 1);                    // LDG latency overlapped with compute
#pragma unroll
        for (int k = 0; k < 16; k++) {
            unsigned long long a2[4];
#pragma unroll
            for (int rp = 0; rp < 4; rp++)
                a2[rp] = *(const unsigned long long*)&As[k][ty * 8 + 2 * rp];
            float4 bA = *(const float4*)&Bs[k][tx * 8];
            float4 bB = *(const float4*)&Bs[k][tx * 8 + 4];
            unsigned long long bb[8];
            bb[0] = packdup(bA.x); bb[1] = packdup(bA.y);
            bb[2] = packdup(bA.z); bb[3] = packdup(bA.w);
            bb[4] = packdup(bB.x); bb[5] = packdup(bB.y);
            bb[6] = packdup(bB.z); bb[7] = packdup(bB.w);
#pragma unroll
            for (int rp = 0; rp < 4; rp++)
#pragma unroll
                for (int j = 0; j < 8; j++)
                    acc[rp][j] = ffma2(a2[rp], bb[j], acc[rp][j]);
        }
        __syncthreads();
        if (more) { storeT(); __syncthreads(); }
    }

    // epilogue: add bias, write two rows per row-pair
    float bias8[8];
#pragma unroll
    for (int j = 0; j < 8; j++) bias8[j] = __ldg(&B[tx * 8 + j]);
#pragma unroll
    for (int rp = 0; rp < 4; rp++) {
        float r0[8], r1[8];
#pragma unroll
        for (int j = 0; j < 8; j++) {
            float lo, hi;
            unpack2(acc[rp][j], lo, hi);
            r0[j] = lo + bias8[j];
            r1[j] = hi + bias8[j];
        }
        int m0 = row0 + ty * 8 + 2 * rp;
        if (m0 < Nn) {
            float4* op = (float4*)(O + (size_t)m0 * 64 + tx * 8);
            op[0] = make_float4(r0[0], r0[1], r0[2], r0[3]);
            op[1] = make_float4(r0[4], r0[5], r0[6], r0[7]);
        }
        if (m0 + 1 < Nn) {
            float4* op = (float4*)(O + (size_t)(m0 + 1) * 64 + tx * 8);
            op[0] = make_float4(r1[0], r1[1], r1[2], r1[3]);
            op[1] = make_float4(r1[4], r1[5], r1[6], r1[7]);
        }
    }
}

// ---------------- kernel 6: GRU gate fusion ----------------
__global__ void k_gates(const float* __restrict__ hidden, float* __restrict__ out) {
    int i = blockIdx.x * blockDim.x + threadIdx.x;
    if (i >= Nn * CHID) return;
    float xr = g_XR[i], hr = g_HR[i];
    float xz = g_XZ[i], hz = g_HZ[i];
    float xn = g_XN[i], h = hidden[i];
    float r = 1.0f / (1.0f + expf(-(xr + hr)));
    float z = 1.0f / (1.0f + expf(-(xz + hz)));
    float n = tanhf(xn + r * hr);                   // faithful to the reference's hr reuse
    out[i] = (1.0f - z) * n + z * h;
}

// ---------------- launch ----------------
extern "C" void kernel_launch(void* const* d_in, const int* in_sizes, int n_in,
                              void* d_out, int out_size) {
    const float* x      = (const float*)d_in[0];
    const float* hidden = (const float*)d_in[1];
    const int*   ei     = (const int*)d_in[2];
    const float* attr   = (const float*)d_in[3];
    const float* Wxr = (const float*)d_in[4];
    const float* Rxr = (const float*)d_in[5];
    const float* Bxr = (const float*)d_in[6];
    const float* Whr = (const float*)d_in[7];
    const float* Rhr = (const float*)d_in[8];
    const float* Bhr = (const float*)d_in[9];
    const float* Wxz = (const float*)d_in[10];
    const float* Rxz = (const float*)d_in[11];
    const float* Bxz = (const float*)d_in[12];
    const float* Whz = (const float*)d_in[13];
    const float* Rhz = (const float*)d_in[14];
    const float* Bhz = (const float*)d_in[15];
    const float* Wxn = (const float*)d_in[16];
    const float* Rxn = (const float*)d_in[17];
    const float* Bxn = (const float*)d_in[18];
    // d_in[19..21] = W_hn/root_hn/b_hn: dead in the reference (hr reuse bug), unused.
    float* out = (float*)d_out;
    (void)in_sizes; (void)n_in; (void)out_size;

    k_zero<<<(Nn + 255) / 256, 256>>>();
    k_edge<<<(Ee + 255) / 256, 256>>>(attr, ei);
    k_scan<<<1, 1024>>>();
    k_fill<<<(Ee + 255) / 256, 256>>>(ei);
    k_scatter<<<Nn, 96>>>(x, hidden, ei);
    dim3 gg((Nn + 63) / 64, 5);
    k_gemm<<<gg, 64>>>(x, hidden,
                       Wxr, Rxr, Bxr,
                       Wxz, Rxz, Bxz,
                       Wxn, Rxn, Bxn,
                       Whr, Rhr, Bhr,
                       Whz, Rhz, Bhz);
    k_gates<<<(Nn * CHID + 255) / 256, 256>>>(hidden, out);
}